// round 15
// baseline (speedup 1.0000x reference)
#include <cuda_runtime.h>

#define N_TOK 1024
#define LDIM  256
#define HDIM  512
#define H2DIM 256

// scratch (allocation-free rule: __device__ globals)
__device__ float g_xr[N_TOK * HDIM];          // concat(l0,l1), tf32-rounded
__device__ float g_wr[2 * HDIM * HDIM];       // W_foh | W_fom, tf32-rounded
__device__ float g_h2r[2 * HDIM * H2DIM];     // hid2, tf32-rounded
__device__ float g_ah[N_TOK * HDIM];          // tanh outputs, tf32-rounded
__device__ float g_am[N_TOK * HDIM];
__device__ float g_At[H2DIM * N_TOK];         // A + hid2Bias, transposed [h2][i]
__device__ float g_Bt[H2DIM * N_TOK];         // B, transposed [h2][j]

__device__ __forceinline__ float tanh_apx(float x) {
    float y;
    asm("tanh.approx.f32 %0, %1;" : "=f"(y) : "f"(x));
    return y;
}

__device__ __forceinline__ unsigned f2tf32(float x) {
    unsigned y;
    asm("cvt.rna.tf32.f32 %0, %1;" : "=r"(y) : "f"(x));
    return y;
}

__device__ __forceinline__ float rnd_tf32(float x) {
    return __uint_as_float(f2tf32(x));
}

__device__ __forceinline__ float4 rnd4(float4 v) {
    float4 r;
    r.x = rnd_tf32(v.x); r.y = rnd_tf32(v.y);
    r.z = rnd_tf32(v.z); r.w = rnd_tf32(v.w);
    return r;
}

// D += A(16x8) * B(8x8), tf32 inputs, fp32 accum
__device__ __forceinline__ void mma_tf32(float* d, const unsigned* a, const unsigned* b) {
    asm("mma.sync.aligned.m16n8k8.row.col.f32.tf32.tf32.f32 "
        "{%0,%1,%2,%3}, {%4,%5,%6,%7}, {%8,%9}, {%0,%1,%2,%3};"
        : "+f"(d[0]), "+f"(d[1]), "+f"(d[2]), "+f"(d[3])
        : "r"(a[0]), "r"(a[1]), "r"(a[2]), "r"(a[3]), "r"(b[0]), "r"(b[1]));
}

__device__ __forceinline__ void cp16(void* dst_smem, const void* src_gmem) {
    unsigned d = (unsigned)__cvta_generic_to_shared(dst_smem);
    asm volatile("cp.async.cg.shared.global [%0], [%1], 16;\n"
                 :: "r"(d), "l"(src_gmem));
}
#define CP_COMMIT()  asm volatile("cp.async.commit_group;\n" ::: "memory")
#define CP_WAIT(n)   asm volatile("cp.async.wait_group %0;\n" :: "n"(n) : "memory")

// ---------------------------------------------------------------------------
// Pre-pass: tf32-round X (concat), W_foh/W_fom, hid2 into device buffers.
// ---------------------------------------------------------------------------
__global__ __launch_bounds__(256) void prep_kernel(
    const float* __restrict__ l0, const float* __restrict__ l1,
    const float* __restrict__ Wfoh, const float* __restrict__ Wfom,
    const float* __restrict__ hid2)
{
    const int nt = gridDim.x * blockDim.x;
    const int t0 = blockIdx.x * blockDim.x + threadIdx.x;

    // X: 1024 rows x 128 float4 (first 64 from l0, next 64 from l1)
    for (int e = t0; e < N_TOK * 128; e += nt) {
        int i = e >> 7, c = e & 127;
        float4 v = (c < 64) ? ((const float4*)l0)[i * 64 + c]
                            : ((const float4*)l1)[i * 64 + (c - 64)];
        ((float4*)g_xr)[e] = rnd4(v);
    }
    // W: 2 x 65536 float4
    for (int e = t0; e < 2 * 65536; e += nt) {
        float4 v = (e < 65536) ? ((const float4*)Wfoh)[e]
                               : ((const float4*)Wfom)[e - 65536];
        ((float4*)g_wr)[e] = rnd4(v);
    }
    // hid2: 65536 float4
    for (int e = t0; e < 65536; e += nt) {
        ((float4*)g_h2r)[e] = rnd4(((const float4*)hid2)[e]);
    }
}

// ---------------------------------------------------------------------------
// P1 (tf32 MMA, 3-stage cp.async ring): ah/am = tanh(X@W + catBias), tf32-
// rounded on store. CTA 64x64, 256 thr (8 warps, 16x32 each), BK=32.
// Wait rule: for c<=NK-2 one newer group may stay in flight -> CP_WAIT(1);
// at the final chunk nothing newer exists -> CP_WAIT(0).
// grid (16,8,2) = 256 CTAs.
// ---------------------------------------------------------------------------
__global__ __launch_bounds__(256) void p1_kernel(const float* __restrict__ catBias)
{
    const int z = blockIdx.z;
    const float* __restrict__ W = g_wr + z * HDIM * HDIM;
    float* __restrict__ out = z ? g_am : g_ah;
    const int m0 = blockIdx.x * 64;
    const int n0 = blockIdx.y * 64;
    const int tid = threadIdx.x;
    const int lane = tid & 31, warp = tid >> 5;
    const int wm = warp & 3;       // 4 m-chunks of 16
    const int wn = warp >> 2;      // 2 n-chunks of 32
    const int lr = lane >> 2;      // 0..7
    const int lc = lane & 3;       // 0..3

    __shared__ float Xs[3][64][36];   // [m][k]; LDS bank = lr*4+lc (bijective)
    __shared__ float Ws[3][32][72];   // [k][n]; LDS bank = lc*8+lr (bijective)

    const int xrow0 = tid >> 3, xc4 = (tid & 7) * 4;   // rows 0..31
    const int xrow1 = xrow0 + 32;                      // rows 32..63
    const int wkr0 = tid >> 4, wc4 = (tid & 15) * 4;   // k-rows 0..15
    const int wkr1 = wkr0 + 16;                        // k-rows 16..31

    const int NK = HDIM / 32;   // 16 chunks

    auto issue = [&](int buf, int k0) {
        cp16(&Xs[buf][xrow0][xc4], &g_xr[(m0 + xrow0) * HDIM + k0 + xc4]);
        cp16(&Xs[buf][xrow1][xc4], &g_xr[(m0 + xrow1) * HDIM + k0 + xc4]);
        cp16(&Ws[buf][wkr0][wc4], &W[(k0 + wkr0) * HDIM + n0 + wc4]);
        cp16(&Ws[buf][wkr1][wc4], &W[(k0 + wkr1) * HDIM + n0 + wc4]);
        CP_COMMIT();
    };

    float C[4][4] = {};

    issue(0, 0);
    issue(1, 32);
    for (int c = 0; c < NK; c++) {
        const int cur = c % 3;
        if (c + 1 < NK) { CP_WAIT(1); } else { CP_WAIT(0); }   // chunk c retired
        __syncthreads();
        if (c + 2 < NK) issue((c + 2) % 3, (c + 2) * 32);  // buf used at c-1: safe post-barrier

        #pragma unroll
        for (int ks = 0; ks < 32; ks += 8) {
            unsigned a[4], b[4][2];
            const int r = wm * 16 + lr;
            a[0] = __float_as_uint(Xs[cur][r][ks + lc]);
            a[1] = __float_as_uint(Xs[cur][r + 8][ks + lc]);
            a[2] = __float_as_uint(Xs[cur][r][ks + lc + 4]);
            a[3] = __float_as_uint(Xs[cur][r + 8][ks + lc + 4]);
            #pragma unroll
            for (int nt = 0; nt < 4; nt++) {
                int cn = wn * 32 + nt * 8 + lr;
                b[nt][0] = __float_as_uint(Ws[cur][ks + lc][cn]);
                b[nt][1] = __float_as_uint(Ws[cur][ks + lc + 4][cn]);
            }
            #pragma unroll
            for (int nt = 0; nt < 4; nt++)
                mma_tf32(C[nt], a, b[nt]);
        }
    }

    #pragma unroll
    for (int nt = 0; nt < 4; nt++) {
        int row = m0 + wm * 16 + lr;
        int col = n0 + wn * 32 + nt * 8 + 2 * lc;
        float cb0 = catBias[z * HDIM + col];
        float cb1 = catBias[z * HDIM + col + 1];
        out[row * HDIM + col]           = rnd_tf32(tanh_apx(C[nt][0] + cb0));
        out[row * HDIM + col + 1]       = rnd_tf32(tanh_apx(C[nt][1] + cb1));
        out[(row + 8) * HDIM + col]     = rnd_tf32(tanh_apx(C[nt][2] + cb0));
        out[(row + 8) * HDIM + col + 1] = rnd_tf32(tanh_apx(C[nt][3] + cb1));
    }
}

// ---------------------------------------------------------------------------
// P2 (tf32 MMA, 3-stage cp.async ring): At[h2][i] = ah@hid2[0:H] + bias (z=0)
//                                       Bt[h2][j] = am@hid2[H:2H]       (z=1)
// CTA 32x64, 128 thr (4 warps: 2x2, each 16x32), BK=32. grid (32,4,2)=256.
// Output TRANSPOSED fp32.
// ---------------------------------------------------------------------------
__global__ __launch_bounds__(128) void p2_kernel(const float* __restrict__ hid2Bias)
{
    const int z = blockIdx.z;
    const float* __restrict__ src = z ? g_am : g_ah;
    const float* __restrict__ W = g_h2r + z * HDIM * H2DIM;
    float* __restrict__ outp = z ? g_Bt : g_At;
    const int m0 = blockIdx.x * 32;
    const int n0 = blockIdx.y * 64;
    const int tid = threadIdx.x;
    const int lane = tid & 31, warp = tid >> 5;
    const int wm = warp & 1;       // 2 m-chunks of 16
    const int wn = warp >> 1;      // 2 n-chunks of 32
    const int lr = lane >> 2;
    const int lc = lane & 3;

    __shared__ float Xs[3][32][36];
    __shared__ float Ws[3][32][72];

    const int xrow0 = tid >> 3, xc4 = (tid & 7) * 4;   // rows 0..15
    const int xrow1 = xrow0 + 16;                      // rows 16..31
    const int wkr = tid >> 4, wc4 = (tid & 15) * 4;    // k-rows 0..7 (+8,+16,+24)

    const int NK = HDIM / 32;   // 16

    auto issue = [&](int buf, int k0) {
        cp16(&Xs[buf][xrow0][xc4], &src[(m0 + xrow0) * HDIM + k0 + xc4]);
        cp16(&Xs[buf][xrow1][xc4], &src[(m0 + xrow1) * HDIM + k0 + xc4]);
        #pragma unroll
        for (int q = 0; q < 4; q++)
            cp16(&Ws[buf][wkr + q * 8][wc4],
                 &W[(k0 + wkr + q * 8) * H2DIM + n0 + wc4]);
        CP_COMMIT();
    };

    float C[4][4] = {};

    issue(0, 0);
    issue(1, 32);
    for (int c = 0; c < NK; c++) {
        const int cur = c % 3;
        if (c + 1 < NK) { CP_WAIT(1); } else { CP_WAIT(0); }   // chunk c retired
        __syncthreads();
        if (c + 2 < NK) issue((c + 2) % 3, (c + 2) * 32);

        #pragma unroll
        for (int ks = 0; ks < 32; ks += 8) {
            unsigned a[4], b[4][2];
            const int r = wm * 16 + lr;
            a[0] = __float_as_uint(Xs[cur][r][ks + lc]);
            a[1] = __float_as_uint(Xs[cur][r + 8][ks + lc]);
            a[2] = __float_as_uint(Xs[cur][r][ks + lc + 4]);
            a[3] = __float_as_uint(Xs[cur][r + 8][ks + lc + 4]);
            #pragma unroll
            for (int nt = 0; nt < 4; nt++) {
                int cn = wn * 32 + nt * 8 + lr;
                b[nt][0] = __float_as_uint(Ws[cur][ks + lc][cn]);
                b[nt][1] = __float_as_uint(Ws[cur][ks + lc + 4][cn]);
            }
            #pragma unroll
            for (int nt = 0; nt < 4; nt++)
                mma_tf32(C[nt], a, b[nt]);
        }
    }

    #pragma unroll
    for (int nt = 0; nt < 4; nt++) {
        int row = m0 + wm * 16 + lr;               // token index
        int col = n0 + wn * 32 + nt * 8 + 2 * lc;  // h2 index
        float b0 = 0.f, b1 = 0.f;
        if (z == 0) { b0 = hid2Bias[col]; b1 = hid2Bias[col + 1]; }
        outp[col * N_TOK + row]           = C[nt][0] + b0;
        outp[(col + 1) * N_TOK + row]     = C[nt][1] + b1;
        outp[col * N_TOK + row + 8]       = C[nt][2] + b0;
        outp[(col + 1) * N_TOK + row + 8] = C[nt][3] + b1;
    }
}

// ---------------------------------------------------------------------------
// Main pairwise kernel: scores[i][j] = outBias + sum_h tanh(At[h][i]+Bt[h][j])*w[h]
// 64x64 CTA tile, 512 THREADS (2x4 micro per thread) -> 16 warps/CTA,
// 256 CTAs x 16 / 148 ~ 27.7 warps/SM (vs 13.8 at 256 thr). Decisive test of
// MUFU-feed vs MUFU-saturation. Per-output accumulation order unchanged ->
// rel_err bit-identical.
// ---------------------------------------------------------------------------
__global__ __launch_bounds__(512, 2) void pair_kernel(
    const float* __restrict__ outLayer, const float* __restrict__ outBias,
    float* __restrict__ out)
{
    const int j0 = blockIdx.x * 64;
    const int i0 = blockIdx.y * 64;
    const int tid = threadIdx.x;
    const int tx = tid & 15;        // 4 j's
    const int ty = tid >> 4;        // 0..31: 2 i's each

    __shared__ float sA[64][64];
    __shared__ float sB[64][64];
    __shared__ float sw[H2DIM];

    if (tid < H2DIM) sw[tid] = outLayer[tid];

    float acc[2][4] = {};

    for (int h0 = 0; h0 < H2DIM; h0 += 64) {
        #pragma unroll
        for (int q = 0; q < 2; q++) {
            int e = q * 512 + tid;          // float4 units, 1024 per tile
            int r = e >> 4, c4 = e & 15;
            *(float4*)&sA[r][c4 * 4] =
                *(const float4*)&g_At[(h0 + r) * N_TOK + i0 + c4 * 4];
            *(float4*)&sB[r][c4 * 4] =
                *(const float4*)&g_Bt[(h0 + r) * N_TOK + j0 + c4 * 4];
        }
        __syncthreads();

        #pragma unroll 8
        for (int hk = 0; hk < 64; hk++) {
            float2 av = *(const float2*)&sA[hk][ty * 2];
            float4 bv = *(const float4*)&sB[hk][tx * 4];
            float a[2] = {av.x, av.y};
            float b[4] = {bv.x, bv.y, bv.z, bv.w};
            float wv = sw[h0 + hk];
            #pragma unroll
            for (int di = 0; di < 2; di++)
                #pragma unroll
                for (int dj = 0; dj < 4; dj++)
                    acc[di][dj] += wv * tanh_apx(a[di] + b[dj]);
        }
        __syncthreads();
    }

    const float ob = outBias[0];
    #pragma unroll
    for (int di = 0; di < 2; di++) {
        int row = i0 + ty * 2 + di;
        float4 o;
        o.x = acc[di][0] + ob;
        o.y = acc[di][1] + ob;
        o.z = acc[di][2] + ob;
        o.w = acc[di][3] + ob;
        *(float4*)&out[row * N_TOK + j0 + tx * 4] = o;
    }
}

// ---------------------------------------------------------------------------
extern "C" void kernel_launch(void* const* d_in, const int* in_sizes, int n_in,
                              void* d_out, int out_size)
{
    const float* lstms0   = (const float*)d_in[0];  // [1024, 256]
    const float* lstms1   = (const float*)d_in[1];  // [1024, 256]
    const float* W_foh    = (const float*)d_in[2];  // [512, 512]
    const float* W_fom    = (const float*)d_in[3];  // [512, 512]
    const float* catBias  = (const float*)d_in[4];  // [1, 1024]
    const float* hid2     = (const float*)d_in[5];  // [1024, 256]
    const float* hid2Bias = (const float*)d_in[6];  // [1, 256]
    const float* outLayer = (const float*)d_in[7];  // [256, 1]
    const float* outBias  = (const float*)d_in[8];  // [1, 1]
    float* out = (float*)d_out;                     // [1024, 1024]

    prep_kernel<<<512, 256>>>(lstms0, lstms1, W_foh, W_fom, hid2);
    p1_kernel<<<dim3(N_TOK / 64, HDIM / 64, 2), 256>>>(catBias);
    p2_kernel<<<dim3(N_TOK / 32, H2DIM / 64, 2), 128>>>(hid2Bias);
    pair_kernel<<<dim3(N_TOK / 64, N_TOK / 64), 512>>>(outLayer, outBias, out);
}

// round 16
// speedup vs baseline: 1.0037x; 1.0037x over previous
#include <cuda_runtime.h>

#define N_TOK 1024
#define LDIM  256
#define HDIM  512
#define H2DIM 256
#define HSPLIT 208   // h < HSPLIT: MUFU tanh path; h >= HSPLIT: rational identity path

// scratch (allocation-free rule: __device__ globals)
__device__ float g_xr[N_TOK * HDIM];          // concat(l0,l1), tf32-rounded
__device__ float g_wr[2 * HDIM * HDIM];       // W_foh | W_fom, tf32-rounded
__device__ float g_h2r[2 * HDIM * H2DIM];     // hid2, tf32-rounded
__device__ float g_ah[N_TOK * HDIM];          // tanh outputs, tf32-rounded
__device__ float g_am[N_TOK * HDIM];
__device__ float g_At[H2DIM * N_TOK];         // A + hid2Bias, transposed [h2][i]
__device__ float g_Bt[H2DIM * N_TOK];         // B, transposed [h2][j]
__device__ float g_tAt[H2DIM * N_TOK];        // tanh(A + hid2Bias)
__device__ float g_tBt[H2DIM * N_TOK];        // tanh(B)

__device__ __forceinline__ float tanh_apx(float x) {
    float y;
    asm("tanh.approx.f32 %0, %1;" : "=f"(y) : "f"(x));
    return y;
}

__device__ __forceinline__ unsigned f2tf32(float x) {
    unsigned y;
    asm("cvt.rna.tf32.f32 %0, %1;" : "=r"(y) : "f"(x));
    return y;
}

__device__ __forceinline__ float rnd_tf32(float x) {
    return __uint_as_float(f2tf32(x));
}

__device__ __forceinline__ float4 rnd4(float4 v) {
    float4 r;
    r.x = rnd_tf32(v.x); r.y = rnd_tf32(v.y);
    r.z = rnd_tf32(v.z); r.w = rnd_tf32(v.w);
    return r;
}

// D += A(16x8) * B(8x8), tf32 inputs, fp32 accum
__device__ __forceinline__ void mma_tf32(float* d, const unsigned* a, const unsigned* b) {
    asm("mma.sync.aligned.m16n8k8.row.col.f32.tf32.tf32.f32 "
        "{%0,%1,%2,%3}, {%4,%5,%6,%7}, {%8,%9}, {%0,%1,%2,%3};"
        : "+f"(d[0]), "+f"(d[1]), "+f"(d[2]), "+f"(d[3])
        : "r"(a[0]), "r"(a[1]), "r"(a[2]), "r"(a[3]), "r"(b[0]), "r"(b[1]));
}

__device__ __forceinline__ void cp16(void* dst_smem, const void* src_gmem) {
    unsigned d = (unsigned)__cvta_generic_to_shared(dst_smem);
    asm volatile("cp.async.cg.shared.global [%0], [%1], 16;\n"
                 :: "r"(d), "l"(src_gmem));
}
#define CP_COMMIT()  asm volatile("cp.async.commit_group;\n" ::: "memory")
#define CP_WAIT(n)   asm volatile("cp.async.wait_group %0;\n" :: "n"(n) : "memory")

// ---------------------------------------------------------------------------
// Pre-pass: tf32-round X (concat), W_foh/W_fom, hid2 into device buffers.
// ---------------------------------------------------------------------------
__global__ __launch_bounds__(256) void prep_kernel(
    const float* __restrict__ l0, const float* __restrict__ l1,
    const float* __restrict__ Wfoh, const float* __restrict__ Wfom,
    const float* __restrict__ hid2)
{
    const int nt = gridDim.x * blockDim.x;
    const int t0 = blockIdx.x * blockDim.x + threadIdx.x;

    for (int e = t0; e < N_TOK * 128; e += nt) {
        int i = e >> 7, c = e & 127;
        float4 v = (c < 64) ? ((const float4*)l0)[i * 64 + c]
                            : ((const float4*)l1)[i * 64 + (c - 64)];
        ((float4*)g_xr)[e] = rnd4(v);
    }
    for (int e = t0; e < 2 * 65536; e += nt) {
        float4 v = (e < 65536) ? ((const float4*)Wfoh)[e]
                               : ((const float4*)Wfom)[e - 65536];
        ((float4*)g_wr)[e] = rnd4(v);
    }
    for (int e = t0; e < 65536; e += nt) {
        ((float4*)g_h2r)[e] = rnd4(((const float4*)hid2)[e]);
    }
}

// ---------------------------------------------------------------------------
// P1 (tf32 MMA, 3-stage cp.async ring): ah/am = tanh(X@W + catBias), tf32-
// rounded on store. CTA 64x64, 256 thr (8 warps, 16x32 each), BK=32.
// grid (16,8,2) = 256 CTAs.
// ---------------------------------------------------------------------------
__global__ __launch_bounds__(256) void p1_kernel(const float* __restrict__ catBias)
{
    const int z = blockIdx.z;
    const float* __restrict__ W = g_wr + z * HDIM * HDIM;
    float* __restrict__ out = z ? g_am : g_ah;
    const int m0 = blockIdx.x * 64;
    const int n0 = blockIdx.y * 64;
    const int tid = threadIdx.x;
    const int lane = tid & 31, warp = tid >> 5;
    const int wm = warp & 3;
    const int wn = warp >> 2;
    const int lr = lane >> 2;
    const int lc = lane & 3;

    __shared__ float Xs[3][64][36];
    __shared__ float Ws[3][32][72];

    const int xrow0 = tid >> 3, xc4 = (tid & 7) * 4;
    const int xrow1 = xrow0 + 32;
    const int wkr0 = tid >> 4, wc4 = (tid & 15) * 4;
    const int wkr1 = wkr0 + 16;

    const int NK = HDIM / 32;

    auto issue = [&](int buf, int k0) {
        cp16(&Xs[buf][xrow0][xc4], &g_xr[(m0 + xrow0) * HDIM + k0 + xc4]);
        cp16(&Xs[buf][xrow1][xc4], &g_xr[(m0 + xrow1) * HDIM + k0 + xc4]);
        cp16(&Ws[buf][wkr0][wc4], &W[(k0 + wkr0) * HDIM + n0 + wc4]);
        cp16(&Ws[buf][wkr1][wc4], &W[(k0 + wkr1) * HDIM + n0 + wc4]);
        CP_COMMIT();
    };

    float C[4][4] = {};

    issue(0, 0);
    issue(1, 32);
    for (int c = 0; c < NK; c++) {
        const int cur = c % 3;
        if (c + 1 < NK) { CP_WAIT(1); } else { CP_WAIT(0); }
        __syncthreads();
        if (c + 2 < NK) issue((c + 2) % 3, (c + 2) * 32);

        #pragma unroll
        for (int ks = 0; ks < 32; ks += 8) {
            unsigned a[4], b[4][2];
            const int r = wm * 16 + lr;
            a[0] = __float_as_uint(Xs[cur][r][ks + lc]);
            a[1] = __float_as_uint(Xs[cur][r + 8][ks + lc]);
            a[2] = __float_as_uint(Xs[cur][r][ks + lc + 4]);
            a[3] = __float_as_uint(Xs[cur][r + 8][ks + lc + 4]);
            #pragma unroll
            for (int nt = 0; nt < 4; nt++) {
                int cn = wn * 32 + nt * 8 + lr;
                b[nt][0] = __float_as_uint(Ws[cur][ks + lc][cn]);
                b[nt][1] = __float_as_uint(Ws[cur][ks + lc + 4][cn]);
            }
            #pragma unroll
            for (int nt = 0; nt < 4; nt++)
                mma_tf32(C[nt], a, b[nt]);
        }
    }

    #pragma unroll
    for (int nt = 0; nt < 4; nt++) {
        int row = m0 + wm * 16 + lr;
        int col = n0 + wn * 32 + nt * 8 + 2 * lc;
        float cb0 = catBias[z * HDIM + col];
        float cb1 = catBias[z * HDIM + col + 1];
        out[row * HDIM + col]           = rnd_tf32(tanh_apx(C[nt][0] + cb0));
        out[row * HDIM + col + 1]       = rnd_tf32(tanh_apx(C[nt][1] + cb1));
        out[(row + 8) * HDIM + col]     = rnd_tf32(tanh_apx(C[nt][2] + cb0));
        out[(row + 8) * HDIM + col + 1] = rnd_tf32(tanh_apx(C[nt][3] + cb1));
    }
}

// ---------------------------------------------------------------------------
// P2 (tf32 MMA, 3-stage cp.async ring): At[h2][i] = ah@hid2[0:H] + bias (z=0)
//                                       Bt[h2][j] = am@hid2[H:2H]       (z=1)
// Epilogue additionally writes tanh(At)/tanh(Bt) for the pair kernel's
// rational-identity path. CTA 32x64, 128 thr, BK=32. grid (32,4,2)=256.
// ---------------------------------------------------------------------------
__global__ __launch_bounds__(128) void p2_kernel(const float* __restrict__ hid2Bias)
{
    const int z = blockIdx.z;
    const float* __restrict__ src = z ? g_am : g_ah;
    const float* __restrict__ W = g_h2r + z * HDIM * H2DIM;
    float* __restrict__ outp = z ? g_Bt : g_At;
    float* __restrict__ outt = z ? g_tBt : g_tAt;
    const int m0 = blockIdx.x * 32;
    const int n0 = blockIdx.y * 64;
    const int tid = threadIdx.x;
    const int lane = tid & 31, warp = tid >> 5;
    const int wm = warp & 1;
    const int wn = warp >> 1;
    const int lr = lane >> 2;
    const int lc = lane & 3;

    __shared__ float Xs[3][32][36];
    __shared__ float Ws[3][32][72];

    const int xrow0 = tid >> 3, xc4 = (tid & 7) * 4;
    const int xrow1 = xrow0 + 16;
    const int wkr = tid >> 4, wc4 = (tid & 15) * 4;

    const int NK = HDIM / 32;

    auto issue = [&](int buf, int k0) {
        cp16(&Xs[buf][xrow0][xc4], &src[(m0 + xrow0) * HDIM + k0 + xc4]);
        cp16(&Xs[buf][xrow1][xc4], &src[(m0 + xrow1) * HDIM + k0 + xc4]);
        #pragma unroll
        for (int q = 0; q < 4; q++)
            cp16(&Ws[buf][wkr + q * 8][wc4],
                 &W[(k0 + wkr + q * 8) * H2DIM + n0 + wc4]);
        CP_COMMIT();
    };

    float C[4][4] = {};

    issue(0, 0);
    issue(1, 32);
    for (int c = 0; c < NK; c++) {
        const int cur = c % 3;
        if (c + 1 < NK) { CP_WAIT(1); } else { CP_WAIT(0); }
        __syncthreads();
        if (c + 2 < NK) issue((c + 2) % 3, (c + 2) * 32);

        #pragma unroll
        for (int ks = 0; ks < 32; ks += 8) {
            unsigned a[4], b[4][2];
            const int r = wm * 16 + lr;
            a[0] = __float_as_uint(Xs[cur][r][ks + lc]);
            a[1] = __float_as_uint(Xs[cur][r + 8][ks + lc]);
            a[2] = __float_as_uint(Xs[cur][r][ks + lc + 4]);
            a[3] = __float_as_uint(Xs[cur][r + 8][ks + lc + 4]);
            #pragma unroll
            for (int nt = 0; nt < 4; nt++) {
                int cn = wn * 32 + nt * 8 + lr;
                b[nt][0] = __float_as_uint(Ws[cur][ks + lc][cn]);
                b[nt][1] = __float_as_uint(Ws[cur][ks + lc + 4][cn]);
            }
            #pragma unroll
            for (int nt = 0; nt < 4; nt++)
                mma_tf32(C[nt], a, b[nt]);
        }
    }

    #pragma unroll
    for (int nt = 0; nt < 4; nt++) {
        int row = m0 + wm * 16 + lr;
        int col = n0 + wn * 32 + nt * 8 + 2 * lc;
        float b0 = 0.f, b1 = 0.f;
        if (z == 0) { b0 = hid2Bias[col]; b1 = hid2Bias[col + 1]; }
        float v00 = C[nt][0] + b0, v01 = C[nt][1] + b1;
        float v10 = C[nt][2] + b0, v11 = C[nt][3] + b1;
        outp[col * N_TOK + row]           = v00;
        outp[(col + 1) * N_TOK + row]     = v01;
        outp[col * N_TOK + row + 8]       = v10;
        outp[(col + 1) * N_TOK + row + 8] = v11;
        outt[col * N_TOK + row]           = tanh_apx(v00);
        outt[(col + 1) * N_TOK + row]     = tanh_apx(v01);
        outt[col * N_TOK + row + 8]       = tanh_apx(v10);
        outt[(col + 1) * N_TOK + row + 8] = tanh_apx(v11);
    }
}

// ---------------------------------------------------------------------------
// Main pairwise kernel, MUFU/FMA hybrid:
//   h <  HSPLIT(208): acc += w * tanh.approx(A + B)           [MUFU-paced]
//   h >= HSPLIT:      acc += w * (tA+tB)/(1+tA*tB)            [fma/alu only:
//       d via FFMA, reciprocal via bit-trick seed + 2 Newton steps]
// Offload fraction 48/256 balances MUFU (13 cyc/256elem) vs fma (~12.5).
// 64x64 CTA tile, 256 thr, 4x4 micro. grid 16x16 = 256 CTAs.
// ---------------------------------------------------------------------------
__global__ __launch_bounds__(256, 2) void pair_kernel(
    const float* __restrict__ outLayer, const float* __restrict__ outBias,
    float* __restrict__ out)
{
    const int j0 = blockIdx.x * 64;
    const int i0 = blockIdx.y * 64;
    const int tid = threadIdx.x;
    const int tx = tid & 15, ty = tid >> 4;

    __shared__ float sA[64][64];
    __shared__ float sB[64][64];
    __shared__ float sw[H2DIM];

    sw[tid] = outLayer[tid];   // tid covers 0..255 == H2DIM

    float acc[4][4] = {};

    #pragma unroll
    for (int ht = 0; ht < 4; ht++) {
        const int h0 = ht * 64;
        // load: rows with h < HSPLIT get raw A/B; rows >= HSPLIT get tanh'd
        #pragma unroll
        for (int q = 0; q < 4; q++) {
            int e = q * 256 + tid;
            int r = e >> 4, c4 = e & 15;
            int h = h0 + r;
            const float* __restrict__ srcA = (h < HSPLIT) ? g_At : g_tAt;
            const float* __restrict__ srcB = (h < HSPLIT) ? g_Bt : g_tBt;
            *(float4*)&sA[r][c4 * 4] = *(const float4*)&srcA[h * N_TOK + i0 + c4 * 4];
            *(float4*)&sB[r][c4 * 4] = *(const float4*)&srcB[h * N_TOK + j0 + c4 * 4];
        }
        __syncthreads();

        const int mufu_end = (ht < 3) ? 64 : (HSPLIT - h0);   // 64,64,64,16
        #pragma unroll 8
        for (int hk = 0; hk < mufu_end; hk++) {
            float4 av = *(const float4*)&sA[hk][ty * 4];
            float4 bv = *(const float4*)&sB[hk][tx * 4];
            float a[4] = {av.x, av.y, av.z, av.w};
            float b[4] = {bv.x, bv.y, bv.z, bv.w};
            float wv = sw[h0 + hk];
            #pragma unroll
            for (int di = 0; di < 4; di++)
                #pragma unroll
                for (int dj = 0; dj < 4; dj++)
                    acc[di][dj] += wv * tanh_apx(a[di] + b[dj]);
        }
        if (ht == 3) {
            #pragma unroll 8
            for (int hk = HSPLIT - h0; hk < 64; hk++) {
                float4 av = *(const float4*)&sA[hk][ty * 4];   // tanh(A)
                float4 bv = *(const float4*)&sB[hk][tx * 4];   // tanh(B)
                float a[4] = {av.x, av.y, av.z, av.w};
                float b[4] = {bv.x, bv.y, bv.z, bv.w};
                float wv = sw[h0 + hk];
                #pragma unroll
                for (int di = 0; di < 4; di++) {
                    #pragma unroll
                    for (int dj = 0; dj < 4; dj++) {
                        float s = a[di] + b[dj];
                        float d = fmaf(a[di], b[dj], 1.0f);   // d in (~3.6e-3, 2]
                        float r = __uint_as_float(0x7EF311C3u - __float_as_uint(d));
                        r = r * (2.0f - d * r);               // Newton 1
                        r = r * (2.0f - d * r);               // Newton 2: rel err <~2e-4
                        acc[di][dj] = fmaf(wv, s * r, acc[di][dj]);
                    }
                }
            }
        }
        __syncthreads();
    }

    const float ob = outBias[0];
    #pragma unroll
    for (int di = 0; di < 4; di++) {
        int row = i0 + ty * 4 + di;
        float4 o;
        o.x = acc[di][0] + ob;
        o.y = acc[di][1] + ob;
        o.z = acc[di][2] + ob;
        o.w = acc[di][3] + ob;
        *(float4*)&out[row * N_TOK + j0 + tx * 4] = o;
    }
}

// ---------------------------------------------------------------------------
extern "C" void kernel_launch(void* const* d_in, const int* in_sizes, int n_in,
                              void* d_out, int out_size)
{
    const float* lstms0   = (const float*)d_in[0];  // [1024, 256]
    const float* lstms1   = (const float*)d_in[1];  // [1024, 256]
    const float* W_foh    = (const float*)d_in[2];  // [512, 512]
    const float* W_fom    = (const float*)d_in[3];  // [512, 512]
    const float* catBias  = (const float*)d_in[4];  // [1, 1024]
    const float* hid2     = (const float*)d_in[5];  // [1024, 256]
    const float* hid2Bias = (const float*)d_in[6];  // [1, 256]
    const float* outLayer = (const float*)d_in[7];  // [256, 1]
    const float* outBias  = (const float*)d_in[8];  // [1, 1]
    float* out = (float*)d_out;                     // [1024, 1024]

    prep_kernel<<<512, 256>>>(lstms0, lstms1, W_foh, W_fom, hid2);
    p1_kernel<<<dim3(N_TOK / 64, HDIM / 64, 2), 256>>>(catBias);
    p2_kernel<<<dim3(N_TOK / 32, H2DIM / 64, 2), 128>>>(hid2Bias);
    pair_kernel<<<dim3(N_TOK / 64, N_TOK / 64), 256>>>(outLayer, outBias, out);
}